// round 12
// baseline (speedup 1.0000x reference)
#include <cuda_runtime.h>
#include <math.h>

#define N_   16384
#define L_   15
#define K_   64
#define H_   16
#define NY_  15
#define S_   2048
#define NEG  (-1e30f)
#define SEG_ 2048         // DP segments (8 positions each; 16 per dptail block)
#define SEGLEN_ (N_/SEG_) // 8
#define G2_  (SEG_/16)    // 128 matrices after level-1 combine
#define G3_  (G2_/16)     // 8 after level-2

typedef unsigned long long u64;

// ---------------- scratch (device globals; no allocation allowed) ------------
__device__ float g_proj[2][(size_t)N_*64];        // permuted input projections
__device__ float g_hf[(size_t)(N_+16)*L_*H_];     // fwd shifted: [p][d][h] = fwd[d][p-d]
__device__ float g_hb[(size_t)N_*L_*H_];          // bwd transposed: [n][l][h]
__device__ float g_A[N_*16];                      // A[p][d], stride 16
__device__ float g_gtab[15*15];                   // scores[p][p][y] for p<15
__device__ float g_M2[G2_*15*16];                 // level-1 combined matrices
__device__ float g_M3[G3_*15*16];                 // level-2 combined matrices
__device__ int   g_bar1, g_bar2;                  // spin barriers (reset by k_lstm)

// ---------------- fast math helpers -----------------------------------------
__device__ __forceinline__ float tanh_ap(float x) {
    float y; asm("tanh.approx.f32 %0, %1;" : "=f"(y) : "f"(x)); return y;
}
__device__ __forceinline__ float sigm(float x) {
    return fmaf(tanh_ap(0.5f*x), 0.5f, 0.5f);
}
__device__ __forceinline__ u64 pk2(float lo, float hi) {
    u64 r; asm("mov.b64 %0, {%1,%2};" : "=l"(r) : "f"(lo), "f"(hi)); return r;
}
__device__ __forceinline__ u64 fma2(u64 a, u64 b, u64 c) {
    u64 d; asm("fma.rn.f32x2 %0, %1, %2, %3;" : "=l"(d) : "l"(a), "l"(b), "l"(c)); return d;
}
__device__ __forceinline__ float2 upk2(u64 a) {
    float lo, hi; asm("mov.b64 {%0,%1}, %2;" : "=f"(lo), "=f"(hi) : "l"(a));
    float2 v; v.x = lo; v.y = hi; return v;
}
__device__ __forceinline__ float max15(const float x[15]) {
    float a = fmaxf(x[0],x[1]),  b = fmaxf(x[2],x[3]);
    float c = fmaxf(x[4],x[5]),  d = fmaxf(x[6],x[7]);
    float e = fmaxf(x[8],x[9]),  f = fmaxf(x[10],x[11]);
    float g = fmaxf(x[12],x[13]);
    a = fmaxf(a,b); c = fmaxf(c,d); e = fmaxf(e,f); g = fmaxf(g,x[14]);
    a = fmaxf(a,c); e = fmaxf(e,g);
    return fmaxf(a,e);
}
__device__ __forceinline__ float lse15(const float x[15]) {
    float m = max15(x);
    float s0 = __expf(x[0]-m)  + __expf(x[1]-m);
    float s1 = __expf(x[2]-m)  + __expf(x[3]-m);
    float s2 = __expf(x[4]-m)  + __expf(x[5]-m);
    float s3 = __expf(x[6]-m)  + __expf(x[7]-m);
    float s4 = __expf(x[8]-m)  + __expf(x[9]-m);
    float s5 = __expf(x[10]-m) + __expf(x[11]-m);
    float s6 = __expf(x[12]-m) + __expf(x[13]-m);
    float s7 = __expf(x[14]-m);
    s0 += s1; s2 += s3; s4 += s5; s6 += s7;
    s0 += s2; s4 += s6;
    return m + __logf(s0 + s4);
}

// ---------------- K1: input projection (2 small GEMMs) -----------------------
__global__ void __launch_bounds__(128) k_proj(const float* __restrict__ data,
                                              const float* __restrict__ fWih,
                                              const float* __restrict__ bWih,
                                              const float* __restrict__ fbih,
                                              const float* __restrict__ fbhh,
                                              const float* __restrict__ bbih,
                                              const float* __restrict__ bbhh) {
    const int dir = blockIdx.y;
    const float* Wih = dir ? bWih : fWih;
    const float* bih = dir ? bbih : fbih;
    const float* bhh = dir ? bbhh : fbhh;
    __shared__ __align__(16) float WTs[4096];
    __shared__ float bs[64];
    for (int i = threadIdx.x; i < 4096; i += 128) {
        int k = i >> 6, m = i & 63, j = m >> 2, c = m & 3, r = c*16 + j;
        WTs[i] = Wih[r*64 + k];
    }
    if (threadIdx.x < 64) {
        int j = threadIdx.x >> 2, c = threadIdx.x & 3, r = c*16 + j;
        bs[threadIdx.x] = bih[r] + bhh[r];
    }
    __syncthreads();

    int n = blockIdx.x * 128 + threadIdx.x;
    float d[64];
    const float4* dp = (const float4*)(data + (size_t)n * 64);
#pragma unroll
    for (int i = 0; i < 16; i++) {
        float4 v = dp[i];
        d[i*4+0] = v.x; d[i*4+1] = v.y; d[i*4+2] = v.z; d[i*4+3] = v.w;
    }
    float4* outp = (float4*)(g_proj[dir] + (size_t)n * 64);
    const float4* W4 = (const float4*)WTs;
    for (int mf = 0; mf < 16; mf++) {
        float4 acc = make_float4(bs[mf*4+0], bs[mf*4+1], bs[mf*4+2], bs[mf*4+3]);
#pragma unroll
        for (int k = 0; k < 64; k++) {
            float4 w = W4[k*16 + mf];
            acc.x += d[k]*w.x; acc.y += d[k]*w.y; acc.z += d[k]*w.z; acc.w += d[k]*w.w;
        }
        outp[mf] = acc;
    }
}

// ---------------- K2: 32768 independent 15-step LSTMs (R8 SHFL form) ----------
// fwd (dir 0) writes step-l output of seq n to g_hf[n+l][l][:] (diagonal gather
// pre-applied); bwd (dir 1) writes to g_hb[n][l][:].
__global__ void __launch_bounds__(256) k_lstm(const float* __restrict__ fWhh,
                                              const float* __restrict__ bWhh,
                                              const float* __restrict__ fh0,
                                              const float* __restrict__ fc0,
                                              const float* __restrict__ bh0,
                                              const float* __restrict__ bc0) {
    const int dir = blockIdx.y;
    // reset dptail spin barriers (stream-ordered before k_dptail)
    if (blockIdx.x == 0 && blockIdx.y == 0 && threadIdx.x == 0) {
        g_bar1 = 0; g_bar2 = 0;
    }
    __shared__ __align__(16) float Ws[1024];
    __shared__ float h0s[16], c0s[16];
    const float* Whh = dir ? bWhh : fWhh;
    for (int i = threadIdx.x; i < 1024; i += 256) Ws[i] = Whh[i];
    if (threadIdx.x < 16) {
        h0s[threadIdx.x] = dir ? bh0[threadIdx.x] : fh0[threadIdx.x];
        c0s[threadIdx.x] = dir ? bc0[threadIdx.x] : fc0[threadIdx.x];
    }
    __syncthreads();

    int lane = threadIdx.x & 31;
    int j = lane & 15;
    int gw = blockIdx.x * 8 + (threadIdx.x >> 5);
    int n = gw * 2 + (lane >> 4);

    u64 wi2[8], wf2[8], wg2[8], wo2[8];
#pragma unroll
    for (int k = 0; k < 8; k++) {
        wi2[k] = *(const u64*)&Ws[(0  + j)*16 + 2*k];
        wf2[k] = *(const u64*)&Ws[(16 + j)*16 + 2*k];
        wg2[k] = *(const u64*)&Ws[(32 + j)*16 + 2*k];
        wo2[k] = *(const u64*)&Ws[(48 + j)*16 + 2*k];
    }
    float h[16];
#pragma unroll
    for (int k = 0; k < 16; k++) h[k] = h0s[k];
    float c = c0s[j];

    const float* proj = g_proj[dir];

    for (int l = 0; l < 15; l++) {
        int idx = dir ? max(n - l, 0) : min(n + l, N_ - 1);
        float4 p4 = *(const float4*)(proj + (size_t)idx * 64 + j * 4);
        u64 h2[8];
#pragma unroll
        for (int k = 0; k < 8; k++) h2[k] = pk2(h[2*k], h[2*k+1]);
        u64 ai2 = pk2(p4.x, 0.f), af2 = pk2(p4.y, 0.f);
        u64 ag2 = pk2(p4.z, 0.f), ao2 = pk2(p4.w, 0.f);
#pragma unroll
        for (int k = 0; k < 8; k++) {
            ai2 = fma2(h2[k], wi2[k], ai2);
            af2 = fma2(h2[k], wf2[k], af2);
            ag2 = fma2(h2[k], wg2[k], ag2);
            ao2 = fma2(h2[k], wo2[k], ao2);
        }
        float2 vi = upk2(ai2), vf = upk2(af2), vg = upk2(ag2), vo = upk2(ao2);
        float ai = vi.x + vi.y, af = vf.x + vf.y;
        float ag = vg.x + vg.y, ao = vo.x + vo.y;
        float tg = tanh_ap(ag);
        c = sigm(af)*c + sigm(ai)*tg;
        float hj = sigm(ao)*tanh_ap(c);
        if (dir) g_hb[((size_t)n*L_ + l)*16 + j] = hj;
        else     g_hf[((size_t)(n + l)*L_ + l)*16 + j] = hj;
#pragma unroll
        for (int k = 0; k < 16; k++) h[k] = __shfl_sync(0xffffffffu, hj, k, 16);
    }
}

// ---------------- K3: scores + online logsumexp over y -> A[p][d] -------------
// Register-lean: no sarr[15]; online 2-accumulator LSE; gtab stored in-loop.
// __launch_bounds__(256, 5) pins >= 5 blocks/SM (was 4 at 63 regs).
__global__ void __launch_bounds__(256, 5) k_scores(const float* __restrict__ Yenc,
                                                   const float* __restrict__ Zenc,
                                                   const float* __restrict__ VW,
                                                   const float* __restrict__ Vb,
                                                   const float* __restrict__ WW,
                                                   const float* __restrict__ Wb) {
    __shared__ __align__(16) float V1S[512];   // [h][32]
    __shared__ __align__(8)  float ypS[240];   // [y][16]
    __shared__ __align__(8)  float zbS[240];   // [d][16]
    __shared__ float Wsh[16];
    __shared__ float Wbs;
    int t = threadIdx.y * 16 + threadIdx.x;
    for (int i = t; i < 512; i += 256) {
        int h = i >> 5, k = i & 31;
        V1S[i] = VW[h*68 + k];
    }
    if (t < 240) {
        int y = t >> 4, h = t & 15;
        float s = 0.0f;
        for (int u = 0; u < 32; u++) s += Yenc[y*32 + u] * VW[h*68 + 32 + u];
        ypS[t] = s;
        float z = Vb[h];
        for (int u = 0; u < 4; u++) z += Zenc[y*4 + u] * VW[h*68 + 64 + u];
        zbS[t] = z;
    }
    if (t < 16)  Wsh[t] = WW[t];
    if (t == 0)  Wbs = Wb[0];
    __syncthreads();

    int d = threadIdx.x;
    int p = blockIdx.x * 16 + threadIdx.y;
    if (d >= 15) return;

    u64 fg2[8], bw2[8];
    const ulonglong2* f4 = (const ulonglong2*)(g_hf + ((size_t)p*L_ + d)*16);
    const ulonglong2* b4 = (const ulonglong2*)(g_hb + ((size_t)p*L_ + d)*16);
#pragma unroll
    for (int i = 0; i < 4; i++) {
        ulonglong2 v = f4[i]; fg2[2*i] = v.x; fg2[2*i+1] = v.y;
        ulonglong2 u = b4[i]; bw2[2*i] = u.x; bw2[2*i+1] = u.y;
    }
    float bse[16];
#pragma unroll
    for (int h = 0; h < 16; h++) {
        u64 acc = pk2(zbS[d*16 + h], 0.0f);
#pragma unroll
        for (int k = 0; k < 8; k++)
            acc = fma2(fg2[k], *(const u64*)&V1S[h*32 + 2*k], acc);
#pragma unroll
        for (int k = 0; k < 8; k++)
            acc = fma2(bw2[k], *(const u64*)&V1S[h*32 + 16 + 2*k], acc);
        float2 a = upk2(acc);
        bse[h] = a.x + a.y;
    }

    const bool gt = (p < 15) && (d == p);
    float m0 = NEG, s0 = 0.0f, m1 = NEG, s1 = 0.0f;
#pragma unroll
    for (int y = 0; y < 15; y++) {
        float s = Wbs;
#pragma unroll
        for (int h = 0; h < 16; h++)
            s = fmaf(Wsh[h], tanh_ap(bse[h] + ypS[y*16 + h]), s);
        if (gt) g_gtab[p*15 + y] = s;
        if (y & 1) {
            float nm = fmaxf(m1, s);
            s1 = fmaf(s1, __expf(m1 - nm), __expf(s - nm));
            m1 = nm;
        } else {
            float nm = fmaxf(m0, s);
            s0 = fmaf(s0, __expf(m0 - nm), __expf(s - nm));
            m0 = nm;
        }
    }
    float m = fmaxf(m0, m1);
    float ssum = fmaf(s0, __expf(m0 - m), s1 * __expf(m1 - m));
    float A = m + __logf(ssum);
    if (d > p) A = NEG;
    g_A[p*16 + d] = A;
}

// ---------------- K4: fused DP tail (dp1 + combine levels + final) ------------
__global__ void __launch_bounds__(256) k_dptail(const int* __restrict__ tags,
                                                const int* __restrict__ lens,
                                                float* __restrict__ out) {
    __shared__ __align__(16) float SM[16][15][16];
    __shared__ float parts[256];
    __shared__ float s_logZ;
    int tid = threadIdx.x;
    int b = blockIdx.x;
    int lane = tid & 31;

    // ---- phase A: per-segment transfer matrices (dp1) ----
    {
        int j = lane & 15;
        int segl = (tid >> 5) * 2 + (lane >> 4);   // 0..15
        int seg = b * 16 + segl;

        float buf[15];
#pragma unroll
        for (int k = 0; k < 15; k++) buf[k] = (j == k) ? 0.0f : NEG;

        const float4* Ar = (const float4*)(g_A + (size_t)seg * SEGLEN_ * 16);
#pragma unroll
        for (int t = 0; t < SEGLEN_; t++) {
            const int hp = (15 - t) % 15;           // compile-time
            float4 q0 = Ar[t*4+0], q1 = Ar[t*4+1], q2 = Ar[t*4+2], q3 = Ar[t*4+3];
            float row[16] = {q0.x,q0.y,q0.z,q0.w, q1.x,q1.y,q1.z,q1.w,
                             q2.x,q2.y,q2.z,q2.w, q3.x,q3.y,q3.z,q3.w};
            float x[15];
#pragma unroll
            for (int k = 0; k < 15; k++) x[k] = row[k] + buf[(hp + k) % 15];
            float nw = lse15(x);
            buf[(hp + 14) % 15] = nw;
        }
        const int HPF = (15 - (SEGLEN_ % 15)) % 15;  // 7
        if (j < 15) {
#pragma unroll
            for (int i = 0; i < 15; i++)
                SM[segl][i][j] = buf[(HPF + i) % 15];
        }
    }
    __syncthreads();

    // ---- phase B: combine 16 smem matrices -> g_M2[b] ----
    {
        int i = lane & 15;
        int ic = min(i, 14);
        int jj = (tid >> 5) * 2 + (lane >> 4);
        float P = SM[0][ic][jj];
#pragma unroll
        for (int tt = 1; tt < 16; tt++) {
            const float4* Mr = (const float4*)&SM[tt][ic][0];
            float4 r0 = Mr[0], r1 = Mr[1], r2 = Mr[2], r3 = Mr[3];
            float row[16] = {r0.x,r0.y,r0.z,r0.w, r1.x,r1.y,r1.z,r1.w,
                             r2.x,r2.y,r2.z,r2.w, r3.x,r3.y,r3.z,r3.w};
            float x[15];
#pragma unroll
            for (int k = 0; k < 15; k++)
                x[k] = row[k] + __shfl_sync(0xffffffffu, P, k, 16);
            P = lse15(x);
        }
        if (i < 15 && jj < 15)
            g_M2[((size_t)b*15 + i)*16 + jj] = P;
    }
    __threadfence();
    __syncthreads();
    if (tid == 0) atomicAdd(&g_bar1, 1);

    // indiv partial sums (block 0, overlapped with other blocks' phase B)
    if (b == 0) {
        float part = 0.0f;
        for (int s = tid; s < S_; s += 256) {
            int l = lens[s];
            if (l < 15) part += g_gtab[(l-1)*15 + tags[s]];
        }
        parts[tid] = part;
    }

    if (b >= 8) return;

    // ---- level-2: blocks 0..7 combine 16 of g_M2 -> g_M3 ----
    if (tid == 0) {
        while (*(volatile int*)&g_bar1 < G2_) __nanosleep(64);
    }
    __syncthreads();
    __threadfence();
    {
        int i = lane & 15;
        int ic = min(i, 14);
        int jj = (tid >> 5) * 2 + (lane >> 4);
        int m0 = b * 16;
        float P = g_M2[((size_t)m0*15 + ic)*16 + jj];
#pragma unroll
        for (int tt = 1; tt < 16; tt++) {
            const float4* Mr = (const float4*)(g_M2 + ((size_t)(m0+tt)*15 + ic)*16);
            float4 r0 = Mr[0], r1 = Mr[1], r2 = Mr[2], r3 = Mr[3];
            float row[16] = {r0.x,r0.y,r0.z,r0.w, r1.x,r1.y,r1.z,r1.w,
                             r2.x,r2.y,r2.z,r2.w, r3.x,r3.y,r3.z,r3.w};
            float x[15];
#pragma unroll
            for (int k = 0; k < 15; k++)
                x[k] = row[k] + __shfl_sync(0xffffffffu, P, k, 16);
            P = lse15(x);
        }
        if (i < 15 && jj < 15)
            g_M3[((size_t)b*15 + i)*16 + jj] = P;
    }
    __threadfence();
    __syncthreads();
    if (tid == 0) atomicAdd(&g_bar2, 1);

    if (b != 0) return;

    // ---- final: block 0 folds 8 matrices + indiv + output ----
    if (tid == 0) {
        while (*(volatile int*)&g_bar2 < G3_) __nanosleep(64);
    }
    __syncthreads();
    __threadfence();
    if (tid < 32) {
        int ii = tid & 15;
        int iic = min(ii, 14);
        float v = (ii == 0) ? 0.0f : NEG;
#pragma unroll
        for (int g = 0; g < G3_; g++) {
            const float4* Mr = (const float4*)(g_M3 + ((size_t)g*15 + iic)*16);
            float4 r0 = Mr[0], r1 = Mr[1], r2 = Mr[2], r3 = Mr[3];
            float row[16] = {r0.x,r0.y,r0.z,r0.w, r1.x,r1.y,r1.z,r1.w,
                             r2.x,r2.y,r2.z,r2.w, r3.x,r3.y,r3.z,r3.w};
            float x[15];
#pragma unroll
            for (int k = 0; k < 15; k++)
                x[k] = row[k] + __shfl_sync(0xffffffffu, v, k, 16);
            v = lse15(x);
        }
        if (tid == 0) s_logZ = v;
    }
    __syncthreads();
    for (int st = 128; st > 0; st >>= 1) {
        if (tid < st) parts[tid] += parts[tid + st];
        __syncthreads();
    }
    if (tid == 0) out[0] = s_logZ - parts[0];
}

// ---------------- launch ------------------------------------------------------
extern "C" void kernel_launch(void* const* d_in, const int* in_sizes, int n_in,
                              void* d_out, int out_size) {
    const float* data   = (const float*)d_in[0];
    const float* fWih   = (const float*)d_in[1];
    const float* fWhh   = (const float*)d_in[2];
    const float* fbih   = (const float*)d_in[3];
    const float* fbhh   = (const float*)d_in[4];
    const float* bWih   = (const float*)d_in[5];
    const float* bWhh   = (const float*)d_in[6];
    const float* bbih   = (const float*)d_in[7];
    const float* bbhh   = (const float*)d_in[8];
    const float* fh0    = (const float*)d_in[9];
    const float* fc0    = (const float*)d_in[10];
    const float* bh0    = (const float*)d_in[11];
    const float* bc0    = (const float*)d_in[12];
    const float* Yenc   = (const float*)d_in[13];
    const float* Zenc   = (const float*)d_in[14];
    const float* VW     = (const float*)d_in[15];
    const float* Vb     = (const float*)d_in[16];
    const float* WW     = (const float*)d_in[17];
    const float* Wb     = (const float*)d_in[18];
    const int*   tags   = (const int*)d_in[19];
    const int*   lens   = (const int*)d_in[20];
    float* out = (float*)d_out;

    k_proj<<<dim3(N_/128, 2), 128>>>(data, fWih, bWih, fbih, fbhh, bbih, bbhh);
    k_lstm<<<dim3(N_/16, 2), 256>>>(fWhh, bWhh, fh0, fc0, bh0, bc0);
    k_scores<<<N_/16, dim3(16, 16)>>>(Yenc, Zenc, VW, Vb, WW, Wb);
    k_dptail<<<G2_, 256>>>(tags, lens, out);
}

// round 13
// speedup vs baseline: 1.2214x; 1.2214x over previous
#include <cuda_runtime.h>
#include <math.h>

#define N_   16384
#define L_   15
#define K_   64
#define H_   16
#define NY_  15
#define S_   2048
#define NEG  (-1e30f)
#define SEG_ 2048         // DP segments (8 positions each; 16 per dptail block)
#define SEGLEN_ (N_/SEG_) // 8
#define G2_  (SEG_/16)    // 128 matrices after level-1 combine
#define G3_  (G2_/16)     // 8 after level-2

typedef unsigned long long u64;

// ---------------- scratch (device globals; no allocation allowed) ------------
__device__ float g_proj[2][(size_t)N_*64];   // permuted input projections
__device__ float g_h[2][(size_t)L_*N_*H_];   // fwd/bwd hidden states [l][n][h]
__device__ float g_A[N_*16];                 // A[p][d], stride 16 (d=15 unused)
__device__ float g_gtab[15*15];              // scores[p][p][y] for p<15
__device__ float g_M2[G2_*15*16];            // level-1 combined matrices
__device__ float g_M3[G3_*15*16];            // level-2 combined matrices
__device__ int   g_bar1, g_bar2;             // spin barriers (reset by k_lstm)

// ---------------- fast math helpers -----------------------------------------
__device__ __forceinline__ float tanh_ap(float x) {
    float y; asm("tanh.approx.f32 %0, %1;" : "=f"(y) : "f"(x)); return y;
}
__device__ __forceinline__ float sigm(float x) {
    return fmaf(tanh_ap(0.5f*x), 0.5f, 0.5f);
}
__device__ __forceinline__ u64 pk2(float lo, float hi) {
    u64 r; asm("mov.b64 %0, {%1,%2};" : "=l"(r) : "f"(lo), "f"(hi)); return r;
}
__device__ __forceinline__ u64 fma2(u64 a, u64 b, u64 c) {
    u64 d; asm("fma.rn.f32x2 %0, %1, %2, %3;" : "=l"(d) : "l"(a), "l"(b), "l"(c)); return d;
}
__device__ __forceinline__ float2 upk2(u64 a) {
    float lo, hi; asm("mov.b64 {%0,%1}, %2;" : "=f"(lo), "=f"(hi) : "l"(a));
    float2 v; v.x = lo; v.y = hi; return v;
}
__device__ __forceinline__ float max15(const float x[15]) {
    float a = fmaxf(x[0],x[1]),  b = fmaxf(x[2],x[3]);
    float c = fmaxf(x[4],x[5]),  d = fmaxf(x[6],x[7]);
    float e = fmaxf(x[8],x[9]),  f = fmaxf(x[10],x[11]);
    float g = fmaxf(x[12],x[13]);
    a = fmaxf(a,b); c = fmaxf(c,d); e = fmaxf(e,f); g = fmaxf(g,x[14]);
    a = fmaxf(a,c); e = fmaxf(e,g);
    return fmaxf(a,e);
}
__device__ __forceinline__ float lse15(const float x[15]) {
    float m = max15(x);
    float s0 = __expf(x[0]-m)  + __expf(x[1]-m);
    float s1 = __expf(x[2]-m)  + __expf(x[3]-m);
    float s2 = __expf(x[4]-m)  + __expf(x[5]-m);
    float s3 = __expf(x[6]-m)  + __expf(x[7]-m);
    float s4 = __expf(x[8]-m)  + __expf(x[9]-m);
    float s5 = __expf(x[10]-m) + __expf(x[11]-m);
    float s6 = __expf(x[12]-m) + __expf(x[13]-m);
    float s7 = __expf(x[14]-m);
    s0 += s1; s2 += s3; s4 += s5; s6 += s7;
    s0 += s2; s4 += s6;
    return m + __logf(s0 + s4);
}

// ---------------- K1: input projection (2 small GEMMs) -----------------------
__global__ void __launch_bounds__(128) k_proj(const float* __restrict__ data,
                                              const float* __restrict__ fWih,
                                              const float* __restrict__ bWih,
                                              const float* __restrict__ fbih,
                                              const float* __restrict__ fbhh,
                                              const float* __restrict__ bbih,
                                              const float* __restrict__ bbhh) {
    const int dir = blockIdx.y;
    const float* Wih = dir ? bWih : fWih;
    const float* bih = dir ? bbih : fbih;
    const float* bhh = dir ? bbhh : fbhh;
    __shared__ __align__(16) float WTs[4096];
    __shared__ float bs[64];
    for (int i = threadIdx.x; i < 4096; i += 128) {
        int k = i >> 6, m = i & 63, j = m >> 2, c = m & 3, r = c*16 + j;
        WTs[i] = Wih[r*64 + k];
    }
    if (threadIdx.x < 64) {
        int j = threadIdx.x >> 2, c = threadIdx.x & 3, r = c*16 + j;
        bs[threadIdx.x] = bih[r] + bhh[r];
    }
    __syncthreads();

    int n = blockIdx.x * 128 + threadIdx.x;
    float d[64];
    const float4* dp = (const float4*)(data + (size_t)n * 64);
#pragma unroll
    for (int i = 0; i < 16; i++) {
        float4 v = dp[i];
        d[i*4+0] = v.x; d[i*4+1] = v.y; d[i*4+2] = v.z; d[i*4+3] = v.w;
    }
    float4* outp = (float4*)(g_proj[dir] + (size_t)n * 64);
    const float4* W4 = (const float4*)WTs;
    for (int mf = 0; mf < 16; mf++) {
        float4 acc = make_float4(bs[mf*4+0], bs[mf*4+1], bs[mf*4+2], bs[mf*4+3]);
#pragma unroll
        for (int k = 0; k < 64; k++) {
            float4 w = W4[k*16 + mf];
            acc.x += d[k]*w.x; acc.y += d[k]*w.y; acc.z += d[k]*w.z; acc.w += d[k]*w.w;
        }
        outp[mf] = acc;
    }
}

// ---------------- K2: 32768 independent 15-step LSTMs -------------------------
// R8 SHFL form + 1-deep software pipeline on the proj loads (next step's LDG
// issued before the current step's compute chain).
__global__ void __launch_bounds__(256) k_lstm(const float* __restrict__ fWhh,
                                              const float* __restrict__ bWhh,
                                              const float* __restrict__ fh0,
                                              const float* __restrict__ fc0,
                                              const float* __restrict__ bh0,
                                              const float* __restrict__ bc0) {
    const int dir = blockIdx.y;
    // reset dptail spin barriers (stream-ordered before k_dptail)
    if (blockIdx.x == 0 && blockIdx.y == 0 && threadIdx.x == 0) {
        g_bar1 = 0; g_bar2 = 0;
    }
    __shared__ __align__(16) float Ws[1024];
    __shared__ float h0s[16], c0s[16];
    const float* Whh = dir ? bWhh : fWhh;
    for (int i = threadIdx.x; i < 1024; i += 256) Ws[i] = Whh[i];
    if (threadIdx.x < 16) {
        h0s[threadIdx.x] = dir ? bh0[threadIdx.x] : fh0[threadIdx.x];
        c0s[threadIdx.x] = dir ? bc0[threadIdx.x] : fc0[threadIdx.x];
    }
    __syncthreads();

    int lane = threadIdx.x & 31;
    int j = lane & 15;
    int gw = blockIdx.x * 8 + (threadIdx.x >> 5);
    int n = gw * 2 + (lane >> 4);

    u64 wi2[8], wf2[8], wg2[8], wo2[8];
#pragma unroll
    for (int k = 0; k < 8; k++) {
        wi2[k] = *(const u64*)&Ws[(0  + j)*16 + 2*k];
        wf2[k] = *(const u64*)&Ws[(16 + j)*16 + 2*k];
        wg2[k] = *(const u64*)&Ws[(32 + j)*16 + 2*k];
        wo2[k] = *(const u64*)&Ws[(48 + j)*16 + 2*k];
    }
    float h[16];
#pragma unroll
    for (int k = 0; k < 16; k++) h[k] = h0s[k];
    float c = c0s[j];

    const float* proj = g_proj[dir];
    float* out = g_h[dir];

    // prefetch step 0 (idx == n for both directions at l=0)
    float4 p4 = *(const float4*)(proj + (size_t)n * 64 + j * 4);

#pragma unroll
    for (int l = 0; l < 15; l++) {
        float4 cur = p4;
        if (l < 14) {
            int idxn = dir ? max(n - (l + 1), 0) : min(n + l + 1, N_ - 1);
            p4 = *(const float4*)(proj + (size_t)idxn * 64 + j * 4);
        }
        u64 h2[8];
#pragma unroll
        for (int k = 0; k < 8; k++) h2[k] = pk2(h[2*k], h[2*k+1]);
        u64 ai2 = pk2(cur.x, 0.f), af2 = pk2(cur.y, 0.f);
        u64 ag2 = pk2(cur.z, 0.f), ao2 = pk2(cur.w, 0.f);
#pragma unroll
        for (int k = 0; k < 8; k++) {
            ai2 = fma2(h2[k], wi2[k], ai2);
            af2 = fma2(h2[k], wf2[k], af2);
            ag2 = fma2(h2[k], wg2[k], ag2);
            ao2 = fma2(h2[k], wo2[k], ao2);
        }
        float2 vi = upk2(ai2), vf = upk2(af2), vg = upk2(ag2), vo = upk2(ao2);
        float ai = vi.x + vi.y, af = vf.x + vf.y;
        float ag = vg.x + vg.y, ao = vo.x + vo.y;
        float tg = tanh_ap(ag);
        c = sigm(af)*c + sigm(ai)*tg;
        float hj = sigm(ao)*tanh_ap(c);
        out[((size_t)l*N_ + n)*16 + j] = hj;
#pragma unroll
        for (int k = 0; k < 16; k++) h[k] = __shfl_sync(0xffffffffu, hj, k, 16);
    }
}

// ---------------- K3: scores + logsumexp over y -> A[p][d] (R6/R8 form) -------
__global__ void __launch_bounds__(256) k_scores(const float* __restrict__ Yenc,
                                                const float* __restrict__ Zenc,
                                                const float* __restrict__ VW,
                                                const float* __restrict__ Vb,
                                                const float* __restrict__ WW,
                                                const float* __restrict__ Wb) {
    __shared__ __align__(16) float V1S[512];   // [h][32]
    __shared__ __align__(8)  float ypS[240];   // [y][16]
    __shared__ __align__(8)  float zbS[240];   // [d][16]
    __shared__ float Wsh[16];
    __shared__ float Wbs;
    int t = threadIdx.y * 16 + threadIdx.x;
    for (int i = t; i < 512; i += 256) {
        int h = i >> 5, k = i & 31;
        V1S[i] = VW[h*68 + k];
    }
    if (t < 240) {
        int y = t >> 4, h = t & 15;
        float s = 0.0f;
        for (int u = 0; u < 32; u++) s += Yenc[y*32 + u] * VW[h*68 + 32 + u];
        ypS[t] = s;
        float z = Vb[h];
        for (int u = 0; u < 4; u++) z += Zenc[y*4 + u] * VW[h*68 + 64 + u];
        zbS[t] = z;
    }
    if (t < 16)  Wsh[t] = WW[t];
    if (t == 0)  Wbs = Wb[0];
    __syncthreads();

    int d = threadIdx.x;
    int p = blockIdx.x * 16 + threadIdx.y;
    if (d >= 15) return;
    int pm = max(p - d, 0);

    u64 fg2[8], bw2[8];
    const ulonglong2* f4 = (const ulonglong2*)(g_h[0] + ((size_t)d*N_ + pm)*16);
    const ulonglong2* b4 = (const ulonglong2*)(g_h[1] + ((size_t)d*N_ + p )*16);
#pragma unroll
    for (int i = 0; i < 4; i++) {
        ulonglong2 v = f4[i]; fg2[2*i] = v.x; fg2[2*i+1] = v.y;
        ulonglong2 u = b4[i]; bw2[2*i] = u.x; bw2[2*i+1] = u.y;
    }
    float bse[16];
#pragma unroll
    for (int h = 0; h < 16; h++) {
        u64 acc = pk2(zbS[d*16 + h], 0.0f);
#pragma unroll
        for (int k = 0; k < 8; k++)
            acc = fma2(fg2[k], *(const u64*)&V1S[h*32 + 2*k], acc);
#pragma unroll
        for (int k = 0; k < 8; k++)
            acc = fma2(bw2[k], *(const u64*)&V1S[h*32 + 16 + 2*k], acc);
        float2 a = upk2(acc);
        bse[h] = a.x + a.y;
    }
    float sarr[15];
#pragma unroll
    for (int y = 0; y < 15; y++) {
        float s = Wbs;
#pragma unroll
        for (int h = 0; h < 16; h++)
            s = fmaf(Wsh[h], tanh_ap(bse[h] + ypS[y*16 + h]), s);
        sarr[y] = s;
    }
    float A = lse15(sarr);
    if (d > p) A = NEG;
    g_A[p*16 + d] = A;
    if (p < 15 && d == p) {
#pragma unroll
        for (int y = 0; y < 15; y++) g_gtab[p*15 + y] = sarr[y];
    }
}

// ---------------- K4: fused DP tail (dp1 + combine levels + final) ------------
__global__ void __launch_bounds__(256) k_dptail(const int* __restrict__ tags,
                                                const int* __restrict__ lens,
                                                float* __restrict__ out) {
    __shared__ __align__(16) float SM[16][15][16];
    __shared__ float parts[256];
    __shared__ float s_logZ;
    int tid = threadIdx.x;
    int b = blockIdx.x;
    int lane = tid & 31;

    // ---- phase A: per-segment transfer matrices (dp1) ----
    {
        int j = lane & 15;
        int segl = (tid >> 5) * 2 + (lane >> 4);   // 0..15
        int seg = b * 16 + segl;

        float buf[15];
#pragma unroll
        for (int k = 0; k < 15; k++) buf[k] = (j == k) ? 0.0f : NEG;

        const float4* Ar = (const float4*)(g_A + (size_t)seg * SEGLEN_ * 16);
#pragma unroll
        for (int t = 0; t < SEGLEN_; t++) {
            const int hp = (15 - t) % 15;           // compile-time
            float4 q0 = Ar[t*4+0], q1 = Ar[t*4+1], q2 = Ar[t*4+2], q3 = Ar[t*4+3];
            float row[16] = {q0.x,q0.y,q0.z,q0.w, q1.x,q1.y,q1.z,q1.w,
                             q2.x,q2.y,q2.z,q2.w, q3.x,q3.y,q3.z,q3.w};
            float x[15];
#pragma unroll
            for (int k = 0; k < 15; k++) x[k] = row[k] + buf[(hp + k) % 15];
            float nw = lse15(x);
            buf[(hp + 14) % 15] = nw;
        }
        const int HPF = (15 - (SEGLEN_ % 15)) % 15;  // 7
        if (j < 15) {
#pragma unroll
            for (int i = 0; i < 15; i++)
                SM[segl][i][j] = buf[(HPF + i) % 15];
        }
    }
    __syncthreads();

    // ---- phase B: combine 16 smem matrices -> g_M2[b] ----
    {
        int i = lane & 15;
        int ic = min(i, 14);
        int jj = (tid >> 5) * 2 + (lane >> 4);
        float P = SM[0][ic][jj];
#pragma unroll
        for (int tt = 1; tt < 16; tt++) {
            const float4* Mr = (const float4*)&SM[tt][ic][0];
            float4 r0 = Mr[0], r1 = Mr[1], r2 = Mr[2], r3 = Mr[3];
            float row[16] = {r0.x,r0.y,r0.z,r0.w, r1.x,r1.y,r1.z,r1.w,
                             r2.x,r2.y,r2.z,r2.w, r3.x,r3.y,r3.z,r3.w};
            float x[15];
#pragma unroll
            for (int k = 0; k < 15; k++)
                x[k] = row[k] + __shfl_sync(0xffffffffu, P, k, 16);
            P = lse15(x);
        }
        if (i < 15 && jj < 15)
            g_M2[((size_t)b*15 + i)*16 + jj] = P;
    }
    __threadfence();
    __syncthreads();
    if (tid == 0) atomicAdd(&g_bar1, 1);

    // indiv partial sums (block 0, overlapped with other blocks' phase B)
    if (b == 0) {
        float part = 0.0f;
        for (int s = tid; s < S_; s += 256) {
            int l = lens[s];
            if (l < 15) part += g_gtab[(l-1)*15 + tags[s]];
        }
        parts[tid] = part;
    }

    if (b >= 8) return;

    // ---- level-2: blocks 0..7 combine 16 of g_M2 -> g_M3 ----
    if (tid == 0) {
        while (*(volatile int*)&g_bar1 < G2_) __nanosleep(64);
    }
    __syncthreads();
    __threadfence();
    {
        int i = lane & 15;
        int ic = min(i, 14);
        int jj = (tid >> 5) * 2 + (lane >> 4);
        int m0 = b * 16;
        float P = g_M2[((size_t)m0*15 + ic)*16 + jj];
#pragma unroll
        for (int tt = 1; tt < 16; tt++) {
            const float4* Mr = (const float4*)(g_M2 + ((size_t)(m0+tt)*15 + ic)*16);
            float4 r0 = Mr[0], r1 = Mr[1], r2 = Mr[2], r3 = Mr[3];
            float row[16] = {r0.x,r0.y,r0.z,r0.w, r1.x,r1.y,r1.z,r1.w,
                             r2.x,r2.y,r2.z,r2.w, r3.x,r3.y,r3.z,r3.w};
            float x[15];
#pragma unroll
            for (int k = 0; k < 15; k++)
                x[k] = row[k] + __shfl_sync(0xffffffffu, P, k, 16);
            P = lse15(x);
        }
        if (i < 15 && jj < 15)
            g_M3[((size_t)b*15 + i)*16 + jj] = P;
    }
    __threadfence();
    __syncthreads();
    if (tid == 0) atomicAdd(&g_bar2, 1);

    if (b != 0) return;

    // ---- final: block 0 folds 8 matrices + indiv + output ----
    if (tid == 0) {
        while (*(volatile int*)&g_bar2 < G3_) __nanosleep(64);
    }
    __syncthreads();
    __threadfence();
    if (tid < 32) {
        int ii = tid & 15;
        int iic = min(ii, 14);
        float v = (ii == 0) ? 0.0f : NEG;
#pragma unroll
        for (int g = 0; g < G3_; g++) {
            const float4* Mr = (const float4*)(g_M3 + ((size_t)g*15 + iic)*16);
            float4 r0 = Mr[0], r1 = Mr[1], r2 = Mr[2], r3 = Mr[3];
            float row[16] = {r0.x,r0.y,r0.z,r0.w, r1.x,r1.y,r1.z,r1.w,
                             r2.x,r2.y,r2.z,r2.w, r3.x,r3.y,r3.z,r3.w};
            float x[15];
#pragma unroll
            for (int k = 0; k < 15; k++)
                x[k] = row[k] + __shfl_sync(0xffffffffu, v, k, 16);
            v = lse15(x);
        }
        if (tid == 0) s_logZ = v;
    }
    __syncthreads();
    for (int st = 128; st > 0; st >>= 1) {
        if (tid < st) parts[tid] += parts[tid + st];
        __syncthreads();
    }
    if (tid == 0) out[0] = s_logZ - parts[0];
}

// ---------------- launch ------------------------------------------------------
extern "C" void kernel_launch(void* const* d_in, const int* in_sizes, int n_in,
                              void* d_out, int out_size) {
    const float* data   = (const float*)d_in[0];
    const float* fWih   = (const float*)d_in[1];
    const float* fWhh   = (const float*)d_in[2];
    const float* fbih   = (const float*)d_in[3];
    const float* fbhh   = (const float*)d_in[4];
    const float* bWih   = (const float*)d_in[5];
    const float* bWhh   = (const float*)d_in[6];
    const float* bbih   = (const float*)d_in[7];
    const float* bbhh   = (const float*)d_in[8];
    const float* fh0    = (const float*)d_in[9];
    const float* fc0    = (const float*)d_in[10];
    const float* bh0    = (const float*)d_in[11];
    const float* bc0    = (const float*)d_in[12];
    const float* Yenc   = (const float*)d_in[13];
    const float* Zenc   = (const float*)d_in[14];
    const float* VW     = (const float*)d_in[15];
    const float* Vb     = (const float*)d_in[16];
    const float* WW     = (const float*)d_in[17];
    const float* Wb     = (const float*)d_in[18];
    const int*   tags   = (const int*)d_in[19];
    const int*   lens   = (const int*)d_in[20];
    float* out = (float*)d_out;

    k_proj<<<dim3(N_/128, 2), 128>>>(data, fWih, bWih, fbih, fbhh, bbih, bbhh);
    k_lstm<<<dim3(N_/16, 2), 256>>>(fWhh, bWhh, fh0, fc0, bh0, bc0);
    k_scores<<<N_/16, dim3(16, 16)>>>(Yenc, Zenc, VW, Vb, WW, Wb);
    k_dptail<<<G2_, 256>>>(tags, lens, out);
}